// round 8
// baseline (speedup 1.0000x reference)
#include <cuda_runtime.h>
#include <cuda_bf16.h>

#define NUM_VERTS 6890
#define NUM_FACES 13776
#define HH 1024
#define WW 1024
#define NB 16
#define HW (HH * WW)

// Element counts (pairwise distinct) used to identify inputs regardless of order.
#define SZ_VERTS  (16 * NUM_VERTS * 3)   // 330720  f32
#define SZ_FACES  (NUM_FACES * 3)        // 41328   idx
#define SZ_PIX    (HW)                   // 1048576 idx
#define SZ_BARY   (HW * 3)               // 3145728 f32

// Precomputed face-vertex attributes: [face*3 + k] -> (x, y, z, pad).
// 13776 * 3 * 16B = 661 KB, L2-resident during the main kernel.
__device__ float4 g_face_attr[NUM_FACES * 3];
// Dtype flags discovered on-device (1 = int64, 0 = int32). Deterministic.
__device__ int g_faces_i64;
__device__ int g_pix_i64;

// ---------------------------------------------------------------------------
// Probe: decide whether index buffers are int64 or int32 — PARALLEL version.
// 64 independent loads per buffer (MLP-saturated, one DRAM round-trip total)
// instead of a serial single-thread chain. Reads only 512 B per buffer, safe
// under either dtype interpretation.
// ---------------------------------------------------------------------------
__global__ void uvr_probe(const void* __restrict__ faces,
                          const void* __restrict__ pix) {
    int w = threadIdx.x >> 5;   // warp id: 0 -> faces, 1 -> pix
    int l = threadIdx.x & 31;
    if (w == 0) {
        const long long* f64 = (const long long*)faces;
        bool bad = false;
#pragma unroll
        for (int i = 0; i < 2; i++) {
            long long v = f64[l + 32 * i];
            bad |= (v < 0 || v >= NUM_VERTS);
        }
        unsigned m = __ballot_sync(0xffffffffu, bad);
        if (l == 0) g_faces_i64 = (m == 0) ? 1 : 0;
    } else {
        const long long* p64 = (const long long*)pix;
        bool bad = false;
#pragma unroll
        for (int i = 0; i < 2; i++) {
            long long v = p64[l + 32 * i];
            bad |= (v < -1 || v >= NUM_FACES);
        }
        unsigned m = __ballot_sync(0xffffffffu, bad);
        if (l == 0) g_pix_i64 = (m == 0) ? 1 : 0;
    }
}

// ---------------------------------------------------------------------------
// Stage 1: collapse face->vertex indirection into an L2-resident table.
// Only batch 0 of verts_attr matters (faithful replication of the reference's
// missing per-batch pixel offset => all batches gather batch-0 face attrs).
// ---------------------------------------------------------------------------
__global__ __launch_bounds__(256) void uvr_build_face_table(
        const float* __restrict__ verts,
        const void*  __restrict__ faces) {
    int i = blockIdx.x * blockDim.x + threadIdx.x;   // over F*3
    if (i >= NUM_FACES * 3) return;
    long long v = g_faces_i64 ? ((const long long*)faces)[i]
                              : (long long)((const int*)faces)[i];
    int vi = (int)v;
    vi = (vi < 0) ? 0 : (vi >= NUM_VERTS ? NUM_VERTS - 1 : vi);  // safety clamp
    const float* p = verts + (size_t)vi * 3;
    g_face_attr[i] = make_float4(p[0], p[1], p[2], 0.0f);
}

// ---------------------------------------------------------------------------
// Stage 2: interpolate + 16-way batch broadcast. 4 pixels/thread.
// Reads are once-only -> __ldcs (don't pollute L2 holding the gather table).
// Output is write-once -> __stcs streaming stores.
// ---------------------------------------------------------------------------
__global__ __launch_bounds__(256) void uvr_render(
        const void*  __restrict__ pixv,   // (H, W) indices
        const float* __restrict__ bary,   // (H, W, 3) f32
        float*       __restrict__ out) {  // (N, H, W, 3) f32
    int t = blockIdx.x * blockDim.x + threadIdx.x;
    int p0 = t * 4;                       // 4 pixels per thread
    if (p0 >= HW) return;

    long long pf[4];
    if (g_pix_i64) {
        longlong2 a = __ldcs(((const longlong2*)pixv) + t * 2);
        longlong2 b = __ldcs(((const longlong2*)pixv) + t * 2 + 1);
        pf[0] = a.x; pf[1] = a.y; pf[2] = b.x; pf[3] = b.y;
    } else {
        int4 a = __ldcs(((const int4*)pixv) + t);
        pf[0] = a.x; pf[1] = a.y; pf[2] = a.z; pf[3] = a.w;
    }

    const float4* bv = reinterpret_cast<const float4*>(bary + (size_t)p0 * 3);
    float4 b0 = __ldcs(bv + 0), b1 = __ldcs(bv + 1), b2 = __ldcs(bv + 2);
    float bc[4][3] = {
        {b0.x, b0.y, b0.z},
        {b0.w, b1.x, b1.y},
        {b1.z, b1.w, b2.x},
        {b2.y, b2.z, b2.w}
    };

    float r[4][3];
#pragma unroll
    for (int i = 0; i < 4; i++) {
        long long f = pf[i];
        float m = (f >= 0) ? 1.0f : 0.0f;
        int idx = (int)f;
        idx = (idx < 0) ? 0 : (idx >= NUM_FACES ? NUM_FACES - 1 : idx);  // clamp
        float4 a0 = g_face_attr[idx * 3 + 0];
        float4 a1 = g_face_attr[idx * 3 + 1];
        float4 a2 = g_face_attr[idx * 3 + 2];
        r[i][0] = m * (bc[i][0] * a0.x + bc[i][1] * a1.x + bc[i][2] * a2.x);
        r[i][1] = m * (bc[i][0] * a0.y + bc[i][1] * a1.y + bc[i][2] * a2.y);
        r[i][2] = m * (bc[i][0] * a0.z + bc[i][1] * a1.z + bc[i][2] * a2.z);
    }

    // Pack 4 pixels * 3 comps = 12 floats into 3 float4 (48 contiguous bytes).
    float4 o0 = make_float4(r[0][0], r[0][1], r[0][2], r[1][0]);
    float4 o1 = make_float4(r[1][1], r[1][2], r[2][0], r[2][1]);
    float4 o2 = make_float4(r[2][2], r[3][0], r[3][1], r[3][2]);

    size_t base = (size_t)p0 * 3;
#pragma unroll
    for (int n = 0; n < NB; n++) {
        float4* op = reinterpret_cast<float4*>(out + (size_t)n * ((size_t)HW * 3) + base);
        __stcs(op + 0, o0);
        __stcs(op + 1, o1);
        __stcs(op + 2, o2);
    }
}

extern "C" void kernel_launch(void* const* d_in, const int* in_sizes, int n_in,
                              void* d_out, int out_size) {
    // Identify inputs by element count (pairwise distinct) — order-proof.
    const float* verts = nullptr;
    const void*  faces = nullptr;
    const void*  pix   = nullptr;
    const float* bary  = nullptr;
    for (int i = 0; i < n_in; i++) {
        switch (in_sizes[i]) {
            case SZ_VERTS: verts = (const float*)d_in[i]; break;
            case SZ_FACES: faces = d_in[i];               break;
            case SZ_PIX:   pix   = d_in[i];               break;
            case SZ_BARY:  bary  = (const float*)d_in[i]; break;
            default: break;
        }
    }
    // Fallback to declared order if size matching failed.
    if (!verts) verts = (const float*)d_in[0];
    if (!faces) faces = d_in[1];
    if (!pix)   pix   = d_in[2];
    if (!bary)  bary  = (const float*)d_in[3];

    float* out = (float*)d_out;
    (void)out_size;

    uvr_probe<<<1, 64>>>(faces, pix);

    {
        int n = NUM_FACES * 3;
        uvr_build_face_table<<<(n + 255) / 256, 256>>>(verts, faces);
    }
    {
        int threads = HW / 4;                 // 262144
        uvr_render<<<threads / 256, 256>>>(pix, bary, out);
    }
}

// round 12
// speedup vs baseline: 1.1207x; 1.1207x over previous
#include <cuda_runtime.h>
#include <cuda_bf16.h>

#define NUM_VERTS 6890
#define NUM_FACES 13776
#define HH 1024
#define WW 1024
#define NB 16
#define HW (HH * WW)

// Element counts (pairwise distinct) used to identify inputs regardless of order.
#define SZ_VERTS  (16 * NUM_VERTS * 3)   // 330720  f32
#define SZ_FACES  (NUM_FACES * 3)        // 41328   idx
#define SZ_PIX    (HW)                   // 1048576 idx
#define SZ_BARY   (HW * 3)               // 3145728 f32

// Precomputed face-vertex attributes: [face*3 + k] -> (x, y, z, pad).
// 13776 * 3 * 16B = 661 KB, L2-resident during the main kernel.
__device__ float4 g_face_attr[NUM_FACES * 3];

// ---------------------------------------------------------------------------
// Per-block dtype probe (no separate launch). Reads the first 64 values of an
// index buffer as int64 — only 512 B, safe under either dtype since the
// smallest index buffer is 41328*4 B. If the data is really int32, the int64
// reinterpretation is astronomically out of range within a few samples.
// Deterministic; L2-broadcast after the first block touches it.
// ---------------------------------------------------------------------------
__device__ __forceinline__ bool probe_is_i64(const void* buf, long long lo,
                                             long long hi, int* s_bad) {
    if (threadIdx.x == 0) *s_bad = 0;
    __syncthreads();
    if (threadIdx.x < 64) {
        long long v = ((const long long*)buf)[threadIdx.x];
        if (v < lo || v >= hi) atomicOr(s_bad, 1);
    }
    __syncthreads();
    return (*s_bad == 0);
}

// ---------------------------------------------------------------------------
// Stage 1: collapse face->vertex indirection into an L2-resident table.
// Only batch 0 of verts_attr matters (faithful replication of the reference's
// missing per-batch pixel offset => all batches gather batch-0 face attrs).
// ---------------------------------------------------------------------------
__global__ __launch_bounds__(256) void uvr_build_face_table(
        const float* __restrict__ verts,
        const void*  __restrict__ faces) {
    __shared__ int s_bad;
    bool i64 = probe_is_i64(faces, 0, NUM_VERTS, &s_bad);

    int i = blockIdx.x * blockDim.x + threadIdx.x;   // over F*3
    if (i >= NUM_FACES * 3) return;
    long long v = i64 ? ((const long long*)faces)[i]
                      : (long long)((const int*)faces)[i];
    int vi = (int)v;
    vi = (vi < 0) ? 0 : (vi >= NUM_VERTS ? NUM_VERTS - 1 : vi);  // safety clamp
    const float* p = verts + (size_t)vi * 3;
    g_face_attr[i] = make_float4(p[0], p[1], p[2], 0.0f);
}

// ---------------------------------------------------------------------------
// Stage 2: interpolate + 16-way batch broadcast. 4 pixels/thread.
// Default cached loads (ldcs on the input streams measurably regressed).
// Output is write-once -> __stcs streaming stores.
// ---------------------------------------------------------------------------
__global__ __launch_bounds__(256) void uvr_render(
        const void*  __restrict__ pixv,   // (H, W) indices
        const float* __restrict__ bary,   // (H, W, 3) f32
        float*       __restrict__ out) {  // (N, H, W, 3) f32
    __shared__ int s_bad;
    bool pix_i64 = probe_is_i64(pixv, -1, NUM_FACES, &s_bad);

    int t = blockIdx.x * blockDim.x + threadIdx.x;
    int p0 = t * 4;                       // 4 pixels per thread
    if (p0 >= HW) return;

    long long pf[4];
    if (pix_i64) {
        longlong2 a = ((const longlong2*)pixv)[t * 2];
        longlong2 b = ((const longlong2*)pixv)[t * 2 + 1];
        pf[0] = a.x; pf[1] = a.y; pf[2] = b.x; pf[3] = b.y;
    } else {
        int4 a = ((const int4*)pixv)[t];
        pf[0] = a.x; pf[1] = a.y; pf[2] = a.z; pf[3] = a.w;
    }

    const float4* bv = reinterpret_cast<const float4*>(bary + (size_t)p0 * 3);
    float4 b0 = bv[0], b1 = bv[1], b2 = bv[2];
    float bc[4][3] = {
        {b0.x, b0.y, b0.z},
        {b0.w, b1.x, b1.y},
        {b1.z, b1.w, b2.x},
        {b2.y, b2.z, b2.w}
    };

    float r[4][3];
#pragma unroll
    for (int i = 0; i < 4; i++) {
        long long f = pf[i];
        float m = (f >= 0) ? 1.0f : 0.0f;
        int idx = (int)f;
        idx = (idx < 0) ? 0 : (idx >= NUM_FACES ? NUM_FACES - 1 : idx);  // clamp
        float4 a0 = g_face_attr[idx * 3 + 0];
        float4 a1 = g_face_attr[idx * 3 + 1];
        float4 a2 = g_face_attr[idx * 3 + 2];
        r[i][0] = m * (bc[i][0] * a0.x + bc[i][1] * a1.x + bc[i][2] * a2.x);
        r[i][1] = m * (bc[i][0] * a0.y + bc[i][1] * a1.y + bc[i][2] * a2.y);
        r[i][2] = m * (bc[i][0] * a0.z + bc[i][1] * a1.z + bc[i][2] * a2.z);
    }

    // Pack 4 pixels * 3 comps = 12 floats into 3 float4 (48 contiguous bytes).
    float4 o0 = make_float4(r[0][0], r[0][1], r[0][2], r[1][0]);
    float4 o1 = make_float4(r[1][1], r[1][2], r[2][0], r[2][1]);
    float4 o2 = make_float4(r[2][2], r[3][0], r[3][1], r[3][2]);

    size_t base = (size_t)p0 * 3;
#pragma unroll
    for (int n = 0; n < NB; n++) {
        float4* op = reinterpret_cast<float4*>(out + (size_t)n * ((size_t)HW * 3) + base);
        __stcs(op + 0, o0);
        __stcs(op + 1, o1);
        __stcs(op + 2, o2);
    }
}

extern "C" void kernel_launch(void* const* d_in, const int* in_sizes, int n_in,
                              void* d_out, int out_size) {
    // Identify inputs by element count (pairwise distinct) — order-proof.
    const float* verts = nullptr;
    const void*  faces = nullptr;
    const void*  pix   = nullptr;
    const float* bary  = nullptr;
    for (int i = 0; i < n_in; i++) {
        switch (in_sizes[i]) {
            case SZ_VERTS: verts = (const float*)d_in[i]; break;
            case SZ_FACES: faces = d_in[i];               break;
            case SZ_PIX:   pix   = d_in[i];               break;
            case SZ_BARY:  bary  = (const float*)d_in[i]; break;
            default: break;
        }
    }
    // Fallback to declared order if size matching failed.
    if (!verts) verts = (const float*)d_in[0];
    if (!faces) faces = d_in[1];
    if (!pix)   pix   = d_in[2];
    if (!bary)  bary  = (const float*)d_in[3];

    float* out = (float*)d_out;
    (void)out_size;

    {
        int n = NUM_FACES * 3;
        uvr_build_face_table<<<(n + 255) / 256, 256>>>(verts, faces);
    }
    {
        int threads = HW / 4;                 // 262144
        uvr_render<<<threads / 256, 256>>>(pix, bary, out);
    }
}